// round 7
// baseline (speedup 1.0000x reference)
#include <cuda_runtime.h>
#include <cstdint>
#include <cstdio>

#define NB   2
#define NN   50000
#define HH   64
#define NE   1000000
#define NOBS 128
#define NA   18
#define NAFF 512
#define NEFF 256
#define PB   196

#define NBLK   148
#define NPAIR  8               // producer/consumer warp pairs per block
#define PAIRS_TOT (NBLK * NPAIR)
#define GROUP  6
#define SLOTS  2               // ring depth per pair
#define WIN    512             // idx window (ints) per pair

typedef unsigned int u32;
typedef unsigned long long ull;

// ---------------- device scratch ----------------
__device__ float g_Wp[128 * 128];
__device__ float g_projG[NB * HH];
__device__ float g_projC[NB * HH];
__device__ int   g_flag[NN];
__device__ int   g_cnt[NN];
__device__ int   g_off[NN + 1];
__device__ int   g_cur[NN];
__device__ int   g_esrc[NE + WIN];            // padded for window overread
__device__ int   g_part[256];
__device__ int   g_base[256];

// ---------------- helpers ----------------
__device__ __forceinline__ void fma2(ull& d, ull a, ull b) {
    asm("fma.rn.f32x2 %0, %1, %2, %0;" : "+l"(d) : "l"(a), "l"(b));
}
__device__ __forceinline__ ull splat2(float w) {
    ull r; unsigned u = __float_as_uint(w);
    asm("mov.b64 %0, {%1, %1};" : "=l"(r) : "r"(u));
    return r;
}
__device__ __forceinline__ ull pack2(float a, float b) {
    ull r;
    asm("mov.b64 %0, {%1, %2};" : "=l"(r) : "r"(__float_as_uint(a)), "r"(__float_as_uint(b)));
    return r;
}
__device__ __forceinline__ float2 u2f2(ull v) {
    float2 f;
    f.x = __uint_as_float((unsigned)v);
    f.y = __uint_as_float((unsigned)(v >> 32));
    return f;
}
__device__ __forceinline__ u32 smem_u32(const void* p) {
    u32 a;
    asm("{ .reg .u64 t; cvta.to.shared.u64 t, %1; cvt.u32.u64 %0, t; }" : "=r"(a) : "l"(p));
    return a;
}
__device__ __forceinline__ void cpa16(void* dst, const void* src) {
    unsigned d = (unsigned)__cvta_generic_to_shared(dst);
    asm volatile("cp.async.cg.shared.global [%0], [%1], 16;" :: "r"(d), "l"(src));
}
#define MBAR_INIT(a, c) asm volatile("mbarrier.init.shared.b64 [%0], %1;" :: "r"(a), "r"(c) : "memory")
#define MBAR_ARRIVE(a)  asm volatile("mbarrier.arrive.shared.b64 _, [%0];" :: "r"(a) : "memory")
#define MBAR_WAIT(mbar_a, par) do { \
    u32 _m = (mbar_a); u32 _p = (par); u32 _done; \
    asm volatile("{\n\t.reg .pred p;\n\tmbarrier.try_wait.parity.acquire.cta.shared::cta.b64 p, [%1], %2;\n\tselp.b32 %0, 1, 0, p;\n\t}" \
        : "=r"(_done) : "r"(_m), "r"(_p) : "memory"); \
    if (!_done) { \
        asm volatile("{\n\t.reg .pred P1;\n\tWL_%=:\n\tmbarrier.try_wait.parity.acquire.cta.shared::cta.b64 P1, [%0], %1, 0x989680;\n\t@P1 bra.uni WD_%=;\n\tbra.uni WL_%=;\n\tWD_%=:\n\t}" \
            :: "r"(_m), "r"(_p) : "memory"); \
    } \
} while (0)

__device__ __forceinline__ int warp_incl_scan(int v) {
    int lane = threadIdx.x & 31;
#pragma unroll
    for (int d = 1; d < 32; d <<= 1) {
        int t = __shfl_up_sync(0xffffffffu, v, d);
        if (lane >= d) v += t;
    }
    return v;
}
__device__ __forceinline__ float sigm(float x) { return __fdividef(1.f, 1.f + __expf(-x)); }
__device__ __forceinline__ float tanha(float x) { return 1.f - __fdividef(2.f, __expf(2.f * x) + 1.f); }

// ---------------- K1a: projections + flags ----------------
__global__ void prep_small_kernel(const float* __restrict__ obs,
                                  const float* __restrict__ W_in,
                                  const float* __restrict__ b_in,
                                  const float* __restrict__ W_gate,
                                  const float* __restrict__ W_cand,
                                  const int* __restrict__ afferent_idx) {
    __shared__ float proj[NB * HH];
    int t = threadIdx.x;            // 128 threads
    int b = t >> 6, h = t & 63;
    float acc = b_in[h];
    for (int o = 0; o < NOBS; o++)
        acc += obs[b * NOBS + o] * W_in[o * HH + h];
    proj[b * HH + h] = acc;
    __syncthreads();
    float ag = 0.f, ac = 0.f;
    for (int k = 0; k < HH; k++) {
        float p = proj[b * HH + k];
        ag += p * W_gate[(HH + k) * HH + h];
        ac += p * W_cand[(HH + k) * HH + h];
    }
    g_projG[b * HH + h] = ag;
    g_projC[b * HH + h] = ac;
    for (int i = t; i < NAFF; i += 128)
        g_flag[afferent_idx[i]] = 1;
}

// ---------------- K1b: fused weight W' ----------------
__global__ void prep_W_kernel(const float* __restrict__ W_msg,
                              const float* __restrict__ W_gate,
                              const float* __restrict__ W_cand) {
    int c = blockIdx.x;
    int k = threadIdx.x;
    float w;
    if (k < HH) {
        w = (c < HH) ? W_gate[k * HH + c] : W_cand[k * HH + (c - HH)];
    } else {
        int km = k - HH;
        float acc = 0.f;
        if (c < HH) {
            for (int t = 0; t < HH; t++)
                acc += W_msg[km * HH + t] * W_gate[(HH + t) * HH + c];
        } else {
            for (int t = 0; t < HH; t++)
                acc += W_msg[km * HH + t] * W_cand[(HH + t) * HH + (c - HH)];
        }
        w = acc;
    }
    g_Wp[k * 128 + c] = w;
}

// ---------------- CSR build ----------------
__global__ void hist_kernel(const int4* __restrict__ dst4) {
    int i = blockIdx.x * blockDim.x + threadIdx.x;
    if (i < NE / 4) {
        int4 d = __ldg(dst4 + i);
        atomicAdd(&g_cnt[d.x], 1);
        atomicAdd(&g_cnt[d.y], 1);
        atomicAdd(&g_cnt[d.z], 1);
        atomicAdd(&g_cnt[d.w], 1);
    }
}

__global__ void scan_part_kernel() {
    int i = blockIdx.x * 256 + threadIdx.x;
    int v = (i < NN) ? g_cnt[i] : 0;
    __shared__ int ws[8];
    int s = v;
#pragma unroll
    for (int d = 16; d > 0; d >>= 1) s += __shfl_down_sync(0xffffffffu, s, d);
    if ((threadIdx.x & 31) == 0) ws[threadIdx.x >> 5] = s;
    __syncthreads();
    if (threadIdx.x == 0) {
        int tot = 0;
        for (int w = 0; w < 8; w++) tot += ws[w];
        g_part[blockIdx.x] = tot;
    }
}

__global__ void scan_mid_kernel() {
    int t = threadIdx.x;
    int lane = t & 31, w = t >> 5;
    int v = (t < PB) ? g_part[t] : 0;
    int inc = warp_incl_scan(v);
    __shared__ int ws[8];
    if (lane == 31) ws[w] = inc;
    __syncthreads();
    if (w == 0) {
        int q = (lane < 8) ? ws[lane] : 0;
        int qi = warp_incl_scan(q);
        if (lane < 8) ws[lane] = qi;
    }
    __syncthreads();
    int base = (w > 0) ? ws[w - 1] : 0;
    g_base[t] = base + inc - v;
}

__global__ void scan_final_kernel() {
    int i = blockIdx.x * 256 + threadIdx.x;
    int t = threadIdx.x;
    int lane = t & 31, w = t >> 5;
    int v = (i < NN) ? g_cnt[i] : 0;
    int inc = warp_incl_scan(v);
    __shared__ int ws[8];
    if (lane == 31) ws[w] = inc;
    __syncthreads();
    if (w == 0) {
        int q = (lane < 8) ? ws[lane] : 0;
        int qi = warp_incl_scan(q);
        if (lane < 8) ws[lane] = qi;
    }
    __syncthreads();
    int base = (w > 0) ? ws[w - 1] : 0;
    int off = g_base[blockIdx.x] + base + inc - v;
    if (i < NN) { g_off[i] = off; g_cur[i] = off; }
    if (i == 0) g_off[NN] = NE;
}

__global__ void scatter_kernel(const int4* __restrict__ src4,
                               const int4* __restrict__ dst4) {
    int i = blockIdx.x * blockDim.x + threadIdx.x;
    if (i < NE / 4) {
        int4 s = __ldg(src4 + i);
        int4 d = __ldg(dst4 + i);
        g_esrc[atomicAdd(&g_cur[d.x], 1)] = s.x;
        g_esrc[atomicAdd(&g_cur[d.y], 1)] = s.y;
        g_esrc[atomicAdd(&g_cur[d.z], 1)] = s.z;
        g_esrc[atomicAdd(&g_cur[d.w], 1)] = s.w;
    }
}

// ---------------- K2: warp-specialized gather||GEMM + GRU epilogue ----------------
// 16 warps = 8 (producer, consumer) pairs. Producers gather node x-rows into a
// depth-2 smem ring; consumers run the f32x2 GEMM tile + epilogue. mbarrier
// full/empty pairs (count=32, all-lane arrive) do the handoff. Producers keep
// the LTS saturated while consumers keep the FMA pipe saturated.
__global__ void __launch_bounds__(512, 1) fused_kernel(const float* __restrict__ state,
                                                       const float* __restrict__ b_gate,
                                                       const float* __restrict__ b_cand,
                                                       float* __restrict__ out_ns) {
    extern __shared__ float smem[];
    float* Ws = smem;                                        // 16384 floats (64KB)
    ull* xs = (ull*)(smem + 16384);                          // NPAIR*SLOTS*GROUP*128 ull (96KB)
    int* sIdx = (int*)(xs + NPAIR * SLOTS * GROUP * 128);    // NPAIR*WIN ints (16KB)
    int* meta = sIdx + NPAIR * WIN;                          // NPAIR*SLOTS*8 ints
    ull* mbars = (ull*)(meta + NPAIR * SLOTS * 8);           // NPAIR*SLOTS*2 mbarriers

    int tid = threadIdx.x;
    for (int i = tid; i < 4096; i += 512)
        ((float4*)Ws)[i] = ((const float4*)g_Wp)[i];
    if (tid < NPAIR * SLOTS * 2)
        MBAR_INIT(smem_u32(mbars + tid), 32);
    __syncthreads();

    int warp = tid >> 5, lane = tid & 31;
    int pair = warp >> 1;
    bool producer = (warp & 1) == 0;

    ull* slabs = xs + pair * (SLOTS * GROUP * 128);
    int* widx = sIdx + pair * WIN;
    int* pmeta = meta + pair * (SLOTS * 8);
    u32 mb = smem_u32(mbars + pair * (SLOTS * 2));
    // full(s) = mb + s*16 ; empty(s) = mb + s*16 + 8

    int gp = blockIdx.x * NPAIR + pair;
    const float2* s0 = (const float2*)state;
    const float2* s1 = s0 + (size_t)NN * 32;

    if (producer) {
        int it = 0;
        for (int base = gp * GROUP; base < NN; base += PAIRS_TOT * GROUP, it++) {
            int st = it & 1;
            int ph = (it >> 1) & 1;
            MBAR_WAIT(mb + st * 16 + 8, ph ^ 1);     // empty wait, phase starts flipped

            int cnt = NN - base;
            if (cnt > GROUP) cnt = GROUP;
            ull* slab = slabs + st * (GROUP * 128);

            // stage contiguous CSR index slab
            int slabo = __ldg(&g_off[base]) & ~3;
            for (int c = lane; c < WIN / 4; c += 32)
                cpa16(widx + c * 4, g_esrc + slabo + c * 4);
            asm volatile("cp.async.commit_group;" ::: "memory");
            asm volatile("cp.async.wait_group 0;" ::: "memory");
            __syncwarp();

            for (int m = 0; m < cnt; m++) {
                int n = base + m;
                int beg = __ldg(&g_off[n]), end = __ldg(&g_off[n + 1]);
                if (lane == 0) pmeta[st * 8 + m] = __ldg(&g_flag[n]);
                float4 acc = make_float4(0.f, 0.f, 0.f, 0.f);
                int j = beg;
                while (j < end) {
                    if (j >= slabo + WIN) {          // refill (rare)
                        slabo = j & ~3;
                        for (int c = lane; c < WIN / 4; c += 32)
                            cpa16(widx + c * 4, g_esrc + slabo + c * 4);
                        asm volatile("cp.async.commit_group;" ::: "memory");
                        asm volatile("cp.async.wait_group 0;" ::: "memory");
                        __syncwarp();
                    }
                    int lim = slabo + WIN;
                    if (lim > end) lim = end;
                    for (; j + 8 <= lim; j += 8) {
                        int e[8];
#pragma unroll
                        for (int u = 0; u < 8; u++) e[u] = widx[j - slabo + u];
                        float2 av[8], bv[8];
#pragma unroll
                        for (int u = 0; u < 8; u++) {
                            av[u] = __ldg(s0 + (size_t)e[u] * 32 + lane);
                            bv[u] = __ldg(s1 + (size_t)e[u] * 32 + lane);
                        }
#pragma unroll
                        for (int u = 0; u < 8; u++) {
                            acc.x += av[u].x; acc.y += av[u].y;
                            acc.z += bv[u].x; acc.w += bv[u].y;
                        }
                    }
                    for (; j < lim; j++) {
                        int e0 = widx[j - slabo];
                        float2 a = __ldg(s0 + (size_t)e0 * 32 + lane);
                        float2 b = __ldg(s1 + (size_t)e0 * 32 + lane);
                        acc.x += a.x; acc.y += a.y; acc.z += b.x; acc.w += b.y;
                    }
                }
                float2 sa = __ldg(s0 + (size_t)n * 32 + lane);
                float2 sb = __ldg(s1 + (size_t)n * 32 + lane);
                ull* row = slab + m * 128;
                ((float4*)row)[lane]        = make_float4(sa.x, sb.x, sa.y, sb.y);
                ((float4*)(row + 64))[lane] = make_float4(acc.x, acc.z, acc.y, acc.w);
            }
            __syncwarp();
            MBAR_ARRIVE(mb + st * 16);               // full arrive (all lanes)
        }
    } else {
        // consumer registers: bias/proj for owned cols
        int q = lane & 15;
        int cc0 = q * 4;
        bool zside = lane < 16;
        float bias[4], pj0[4], pj1[4];
#pragma unroll
        for (int c = 0; c < 4; c++) {
            int cc = cc0 + c;
            if (zside) { bias[c] = __ldg(b_gate + cc); pj0[c] = g_projG[cc]; pj1[c] = g_projG[64 + cc]; }
            else       { bias[c] = __ldg(b_cand + cc); pj0[c] = g_projC[cc]; pj1[c] = g_projC[64 + cc]; }
        }

        int it = 0;
        for (int base = gp * GROUP; base < NN; base += PAIRS_TOT * GROUP, it++) {
            int st = it & 1;
            int ph = (it >> 1) & 1;
            MBAR_WAIT(mb + st * 16, ph);             // full wait

            int cnt = NN - base;
            if (cnt > GROUP) cnt = GROUP;
            ull* mx = slabs + st * (GROUP * 128);

            ull acc6[GROUP][4];
#pragma unroll
            for (int m = 0; m < GROUP; m++)
#pragma unroll
                for (int c = 0; c < 4; c++) acc6[m][c] = 0ull;

#pragma unroll 4
            for (int k = 0; k < 128; k += 2) {
                float4 wA = ((const float4*)(Ws + k * 128))[lane];
                float4 wB = ((const float4*)(Ws + (k + 1) * 128))[lane];
                ull wa0 = splat2(wA.x), wa1 = splat2(wA.y), wa2 = splat2(wA.z), wa3 = splat2(wA.w);
                ull wb0 = splat2(wB.x), wb1 = splat2(wB.y), wb2 = splat2(wB.z), wb3 = splat2(wB.w);
#pragma unroll
                for (int m = 0; m < GROUP; m++) {
                    ulonglong2 xv = ((const ulonglong2*)(mx + m * 128))[k >> 1];
                    fma2(acc6[m][0], wa0, xv.x); fma2(acc6[m][1], wa1, xv.x);
                    fma2(acc6[m][2], wa2, xv.x); fma2(acc6[m][3], wa3, xv.x);
                    fma2(acc6[m][0], wb0, xv.y); fma2(acc6[m][1], wb1, xv.y);
                    fma2(acc6[m][2], wb2, xv.y); fma2(acc6[m][3], wb3, xv.y);
                }
            }

            for (int m = 0; m < cnt; m++) {
                int n = base + m;
                int fl = pmeta[st * 8 + m];
                ull actp[4];
#pragma unroll
                for (int c = 0; c < 4; c++) {
                    float2 pre = u2f2(acc6[m][c]);
                    float p0 = pre.x + bias[c] + (fl ? pj0[c] : 0.f);
                    float p1 = pre.y + bias[c] + (fl ? pj1[c] : 0.f);
                    float a0, a1;
                    if (zside) { a0 = sigm(p0);  a1 = sigm(p1); }
                    else       { a0 = tanha(p0); a1 = tanha(p1); }
                    actp[c] = pack2(a0, a1);
                }
                ull oth[4];
#pragma unroll
                for (int c = 0; c < 4; c++)
                    oth[c] = __shfl_xor_sync(0xffffffffu, actp[c], 16);
                if (zside) {
                    float4 r0, r1;
                    float* q0 = (float*)&r0;
                    float* q1 = (float*)&r1;
#pragma unroll
                    for (int c = 0; c < 4; c++) {
                        float2 z = u2f2(actp[c]);
                        float2 t = u2f2(oth[c]);
                        float2 sp = u2f2(mx[m * 128 + cc0 + c]);
                        q0[c] = fmaf(z.x, t.x - sp.x, sp.x);
                        q1[c] = fmaf(z.y, t.y - sp.y, sp.y);
                    }
                    *((float4*)(out_ns + (size_t)n * 64 + cc0)) = r0;
                    *((float4*)(out_ns + ((size_t)NN + n) * 64 + cc0)) = r1;
                }
            }
            __syncwarp();
            MBAR_ARRIVE(mb + st * 16 + 8);           // empty arrive (all lanes)
        }
    }
}

// ---------------- K4: readout + policy heads ----------------
__global__ void readout_kernel(const float* __restrict__ ns,
                               const int* __restrict__ efferent_idx,
                               const float* __restrict__ W_dec,
                               const float* __restrict__ b_dec,
                               const float* __restrict__ W_mean,
                               const float* __restrict__ b_mean,
                               const float* __restrict__ W_ls,
                               const float* __restrict__ b_ls,
                               float* __restrict__ out) {
    __shared__ float ro[NB * HH];
    __shared__ float dec[NB * HH];
    int t = threadIdx.x;
    int b = t >> 6, h = t & 63;
    float sum = 0.f;
    for (int i = 0; i < NEFF; i++) {
        int idx = efferent_idx[i];
        sum += ns[((size_t)b * NN + idx) * HH + h];
    }
    ro[b * HH + h] = sum * (1.f / NEFF);
    __syncthreads();
    float acc = b_dec[h];
    for (int k = 0; k < HH; k++)
        acc += ro[b * HH + k] * W_dec[k * HH + h];
    dec[b * HH + h] = tanhf(acc);
    __syncthreads();
    if (t < NB * NA) {
        int bb = t / NA, a = t % NA;
        float m = b_mean[a], ls = b_ls[a];
        for (int k = 0; k < HH; k++) {
            float d = dec[bb * HH + k];
            m  += d * W_mean[k * NA + a];
            ls += d * W_ls[k * NA + a];
        }
        ls = fminf(fmaxf(ls, -5.f), 2.f);
        out[bb * NA + a] = m;
        out[NB * NA + bb * NA + a] = ls;
    }
}

// ---------------- launch ----------------
extern "C" void kernel_launch(void* const* d_in, const int* in_sizes, int n_in,
                              void* d_out, int out_size) {
    const float* obs    = (const float*)d_in[0];
    const float* state  = (const float*)d_in[1];
    const float* W_in   = (const float*)d_in[2];
    const float* b_in   = (const float*)d_in[3];
    const float* W_msg  = (const float*)d_in[4];
    const float* W_gate = (const float*)d_in[5];
    const float* b_gate = (const float*)d_in[6];
    const float* W_cand = (const float*)d_in[7];
    const float* b_cand = (const float*)d_in[8];
    const float* W_dec  = (const float*)d_in[9];
    const float* b_dec  = (const float*)d_in[10];
    const float* W_mean = (const float*)d_in[11];
    const float* b_mean = (const float*)d_in[12];
    const float* W_ls   = (const float*)d_in[13];
    const float* b_ls   = (const float*)d_in[14];
    const int* src_idx  = (const int*)d_in[15];
    const int* dst_idx  = (const int*)d_in[16];
    const int* aff_idx  = (const int*)d_in[17];
    const int* eff_idx  = (const int*)d_in[18];
    float* out = (float*)d_out;
    float* out_ns = out + 2 * NB * NA;

    void *cntp = nullptr, *flagp = nullptr;
    cudaGetSymbolAddress(&cntp, g_cnt);
    cudaGetSymbolAddress(&flagp, g_flag);
    cudaMemsetAsync(cntp, 0, sizeof(int) * NN);
    cudaMemsetAsync(flagp, 0, sizeof(int) * NN);

    prep_small_kernel<<<1, 128>>>(obs, W_in, b_in, W_gate, W_cand, aff_idx);
    prep_W_kernel<<<128, 128>>>(W_msg, W_gate, W_cand);

    hist_kernel<<<(NE / 4 + 255) / 256, 256>>>((const int4*)dst_idx);
    scan_part_kernel<<<PB, 256>>>();
    scan_mid_kernel<<<1, 256>>>();
    scan_final_kernel<<<PB, 256>>>();
    scatter_kernel<<<(NE / 4 + 255) / 256, 256>>>((const int4*)src_idx, (const int4*)dst_idx);

    size_t smem = 16384u * 4                                  // Ws
                + (size_t)NPAIR * SLOTS * GROUP * 128 * 8     // x slabs
                + (size_t)NPAIR * WIN * 4                     // idx windows
                + (size_t)NPAIR * SLOTS * 8 * 4               // meta
                + (size_t)NPAIR * SLOTS * 2 * 8;              // mbarriers
    cudaFuncSetAttribute(fused_kernel, cudaFuncAttributeMaxDynamicSharedMemorySize, (int)smem);
    fused_kernel<<<NBLK, 512, smem>>>(state, b_gate, b_cand, out_ns);

    readout_kernel<<<1, 128>>>(out_ns, eff_idx, W_dec, b_dec, W_mean, b_mean, W_ls, b_ls, out);
}

// round 8
// speedup vs baseline: 1.8181x; 1.8181x over previous
#include <cuda_runtime.h>
#include <cuda_fp16.h>
#include <cstdint>
#include <cstdio>

#define NB   2
#define NN   50000
#define HH   64
#define NE   1000000
#define NOBS 128
#define NA   18
#define NAFF 512
#define NEFF 256
#define PB   196

#define NBLK   148
#define NW     16
#define WTOT   (NBLK * NW)     // 2368 warps
#define GROUP  6
#define WIN    512             // idx window (ints) per warp

typedef unsigned int u32;
typedef unsigned long long ull;

// ---------------- device scratch ----------------
__device__ float g_Wp[128 * 128];             // fused weight
__device__ ull   g_shalf[(size_t)NN * 32];    // fp16-packed state rows: [n][lane] = {h2(b0 k2l,k2l+1), h2(b1 ...)}
__device__ float g_projG[NB * HH];
__device__ float g_projC[NB * HH];
__device__ int   g_flag[NN];
__device__ int   g_cnt[NN];
__device__ int   g_off[NN + 1];
__device__ int   g_cur[NN];
__device__ int   g_esrc[NE + WIN];            // padded for cp.async overread
__device__ int   g_part[256];
__device__ int   g_base[256];

// ---------------- helpers ----------------
__device__ __forceinline__ void fma2(ull& d, ull a, ull b) {
    asm("fma.rn.f32x2 %0, %1, %2, %0;" : "+l"(d) : "l"(a), "l"(b));
}
__device__ __forceinline__ void add2(ull& d, ull a) {
    asm("add.rn.f32x2 %0, %0, %1;" : "+l"(d) : "l"(a));
}
__device__ __forceinline__ ull splat2(float w) {
    ull r; unsigned u = __float_as_uint(w);
    asm("mov.b64 %0, {%1, %1};" : "=l"(r) : "r"(u));
    return r;
}
__device__ __forceinline__ ull pack2(float a, float b) {
    ull r;
    asm("mov.b64 %0, {%1, %2};" : "=l"(r) : "r"(__float_as_uint(a)), "r"(__float_as_uint(b)));
    return r;
}
__device__ __forceinline__ float2 u2f2(ull v) {
    float2 f;
    f.x = __uint_as_float((unsigned)v);
    f.y = __uint_as_float((unsigned)(v >> 32));
    return f;
}
__device__ __forceinline__ void cpa16(void* dst, const void* src) {
    unsigned d = (unsigned)__cvta_generic_to_shared(dst);
    asm volatile("cp.async.cg.shared.global [%0], [%1], 16;" :: "r"(d), "l"(src));
}
__device__ __forceinline__ int warp_incl_scan(int v) {
    int lane = threadIdx.x & 31;
#pragma unroll
    for (int d = 1; d < 32; d <<= 1) {
        int t = __shfl_up_sync(0xffffffffu, v, d);
        if (lane >= d) v += t;
    }
    return v;
}
__device__ __forceinline__ float sigm(float x) { return __fdividef(1.f, 1.f + __expf(-x)); }
__device__ __forceinline__ float tanha(float x) { return 1.f - __fdividef(2.f, __expf(2.f * x) + 1.f); }

// ---------------- K1a: projections + flags ----------------
__global__ void prep_small_kernel(const float* __restrict__ obs,
                                  const float* __restrict__ W_in,
                                  const float* __restrict__ b_in,
                                  const float* __restrict__ W_gate,
                                  const float* __restrict__ W_cand,
                                  const int* __restrict__ afferent_idx) {
    __shared__ float proj[NB * HH];
    int t = threadIdx.x;            // 128 threads
    int b = t >> 6, h = t & 63;
    float acc = b_in[h];
    for (int o = 0; o < NOBS; o++)
        acc += obs[b * NOBS + o] * W_in[o * HH + h];
    proj[b * HH + h] = acc;
    __syncthreads();
    float ag = 0.f, ac = 0.f;
    for (int k = 0; k < HH; k++) {
        float p = proj[b * HH + k];
        ag += p * W_gate[(HH + k) * HH + h];
        ac += p * W_cand[(HH + k) * HH + h];
    }
    g_projG[b * HH + h] = ag;
    g_projC[b * HH + h] = ac;
    for (int i = t; i < NAFF; i += 128)
        g_flag[afferent_idx[i]] = 1;
}

// ---------------- K1b: fused weight W' ----------------
__global__ void prep_W_kernel(const float* __restrict__ W_msg,
                              const float* __restrict__ W_gate,
                              const float* __restrict__ W_cand) {
    int c = blockIdx.x;
    int k = threadIdx.x;
    float w;
    if (k < HH) {
        w = (c < HH) ? W_gate[k * HH + c] : W_cand[k * HH + (c - HH)];
    } else {
        int km = k - HH;
        float acc = 0.f;
        if (c < HH) {
            for (int t = 0; t < HH; t++)
                acc += W_msg[km * HH + t] * W_gate[(HH + t) * HH + c];
        } else {
            for (int t = 0; t < HH; t++)
                acc += W_msg[km * HH + t] * W_cand[(HH + t) * HH + (c - HH)];
        }
        w = acc;
    }
    g_Wp[k * 128 + c] = w;
}

// ---------------- conv: pack state into fp16 pair rows ----------------
__global__ void conv_kernel(const float* __restrict__ state) {
    int i = blockIdx.x * 256 + threadIdx.x;
    if (i >= NN * 32) return;
    int n = i >> 5, l = i & 31;
    const float2* s0 = (const float2*)state;
    const float2* s1 = s0 + (size_t)NN * 32;
    float2 a = __ldg(s0 + (size_t)n * 32 + l);   // b0: k=2l, 2l+1
    float2 b = __ldg(s1 + (size_t)n * 32 + l);   // b1
    __half2 ha = __floats2half2_rn(a.x, a.y);
    __half2 hb = __floats2half2_rn(b.x, b.y);
    u32 la = *(u32*)&ha, lb = *(u32*)&hb;
    g_shalf[(size_t)n * 32 + l] = (ull)la | ((ull)lb << 32);
}

// ---------------- CSR build ----------------
__global__ void hist_kernel(const int4* __restrict__ dst4) {
    int i = blockIdx.x * blockDim.x + threadIdx.x;
    if (i < NE / 4) {
        int4 d = __ldg(dst4 + i);
        atomicAdd(&g_cnt[d.x], 1);
        atomicAdd(&g_cnt[d.y], 1);
        atomicAdd(&g_cnt[d.z], 1);
        atomicAdd(&g_cnt[d.w], 1);
    }
}

__global__ void scan_part_kernel() {
    int i = blockIdx.x * 256 + threadIdx.x;
    int v = (i < NN) ? g_cnt[i] : 0;
    __shared__ int ws[8];
    int s = v;
#pragma unroll
    for (int d = 16; d > 0; d >>= 1) s += __shfl_down_sync(0xffffffffu, s, d);
    if ((threadIdx.x & 31) == 0) ws[threadIdx.x >> 5] = s;
    __syncthreads();
    if (threadIdx.x == 0) {
        int tot = 0;
        for (int w = 0; w < 8; w++) tot += ws[w];
        g_part[blockIdx.x] = tot;
    }
}

__global__ void scan_mid_kernel() {
    int t = threadIdx.x;
    int lane = t & 31, w = t >> 5;
    int v = (t < PB) ? g_part[t] : 0;
    int inc = warp_incl_scan(v);
    __shared__ int ws[8];
    if (lane == 31) ws[w] = inc;
    __syncthreads();
    if (w == 0) {
        int q = (lane < 8) ? ws[lane] : 0;
        int qi = warp_incl_scan(q);
        if (lane < 8) ws[lane] = qi;
    }
    __syncthreads();
    int base = (w > 0) ? ws[w - 1] : 0;
    g_base[t] = base + inc - v;
}

__global__ void scan_final_kernel() {
    int i = blockIdx.x * 256 + threadIdx.x;
    int t = threadIdx.x;
    int lane = t & 31, w = t >> 5;
    int v = (i < NN) ? g_cnt[i] : 0;
    int inc = warp_incl_scan(v);
    __shared__ int ws[8];
    if (lane == 31) ws[w] = inc;
    __syncthreads();
    if (w == 0) {
        int q = (lane < 8) ? ws[lane] : 0;
        int qi = warp_incl_scan(q);
        if (lane < 8) ws[lane] = qi;
    }
    __syncthreads();
    int base = (w > 0) ? ws[w - 1] : 0;
    int off = g_base[blockIdx.x] + base + inc - v;
    if (i < NN) { g_off[i] = off; g_cur[i] = off; }
    if (i == 0) g_off[NN] = NE;
}

__global__ void scatter_kernel(const int4* __restrict__ src4,
                               const int4* __restrict__ dst4) {
    int i = blockIdx.x * blockDim.x + threadIdx.x;
    if (i < NE / 4) {
        int4 s = __ldg(src4 + i);
        int4 d = __ldg(dst4 + i);
        g_esrc[atomicAdd(&g_cur[d.x], 1)] = s.x;
        g_esrc[atomicAdd(&g_cur[d.y], 1)] = s.y;
        g_esrc[atomicAdd(&g_cur[d.z], 1)] = s.z;
        g_esrc[atomicAdd(&g_cur[d.w], 1)] = s.w;
    }
}

// ---------------- K2: fused gather + f32x2 GEMM + GRU epilogue ----------------
// 16 warps/block, 1 block/SM, no block syncs in the loop. Gather reads the
// fp16-packed rows (256B/edge) with an 8-edge unroll and f32x2 accumulate;
// own-state rows stay exact fp32.
__global__ void __launch_bounds__(512, 1) fused_kernel(const float* __restrict__ state,
                                                       const float* __restrict__ b_gate,
                                                       const float* __restrict__ b_cand,
                                                       float* __restrict__ out_ns) {
    extern __shared__ float smem[];
    float* Ws = smem;                                    // 16384 floats
    ull* xs = (ull*)(smem + 16384);                      // NW * GROUP * 128 ull
    int* sIdx = (int*)(xs + NW * GROUP * 128);           // NW * WIN ints

    int tid = threadIdx.x;
    for (int i = tid; i < 4096; i += 512)
        ((float4*)Ws)[i] = ((const float4*)g_Wp)[i];
    __syncthreads();

    int warp = tid >> 5, lane = tid & 31;
    int q = lane & 15;
    int cc0 = q * 4;
    bool zside = lane < 16;

    float bias[4], pj0[4], pj1[4];
#pragma unroll
    for (int c = 0; c < 4; c++) {
        int cc = cc0 + c;
        if (zside) { bias[c] = __ldg(b_gate + cc); pj0[c] = g_projG[cc]; pj1[c] = g_projG[64 + cc]; }
        else       { bias[c] = __ldg(b_cand + cc); pj0[c] = g_projC[cc]; pj1[c] = g_projC[64 + cc]; }
    }

    ull* mx = xs + warp * (GROUP * 128);
    int* widx = sIdx + warp * WIN;
    int gwid = blockIdx.x * NW + warp;
    const float2* s0 = (const float2*)state;
    const float2* s1 = s0 + (size_t)NN * 32;
    const ull* sh = g_shalf;

    for (int base = gwid * GROUP; base < NN; base += WTOT * GROUP) {
        int cnt = NN - base;
        if (cnt > GROUP) cnt = GROUP;
        int flg[GROUP];

        // ---- stage index slab (contiguous CSR range for this group) ----
        int slab = __ldg(&g_off[base]) & ~3;
        for (int c = lane; c < WIN / 4; c += 32)
            cpa16(widx + c * 4, g_esrc + slab + c * 4);
        asm volatile("cp.async.commit_group;" ::: "memory");
        asm volatile("cp.async.wait_group 0;" ::: "memory");
        __syncwarp();

        // ---- gather phase (fp16 rows, f32x2 accumulate) ----
        for (int m = 0; m < cnt; m++) {
            int n = base + m;
            int beg = __ldg(&g_off[n]), end = __ldg(&g_off[n + 1]);
            flg[m] = __ldg(&g_flag[n]);
            ull accA = 0ull, accB = 0ull;      // f32x2: (b0 k2l, b0 k2l+1), (b1 ...)
            int j = beg;
            while (j < end) {
                if (j >= slab + WIN) {           // refill window (rare)
                    slab = j & ~3;
                    for (int c = lane; c < WIN / 4; c += 32)
                        cpa16(widx + c * 4, g_esrc + slab + c * 4);
                    asm volatile("cp.async.commit_group;" ::: "memory");
                    asm volatile("cp.async.wait_group 0;" ::: "memory");
                    __syncwarp();
                }
                int lim = slab + WIN;
                if (lim > end) lim = end;
                for (; j + 8 <= lim; j += 8) {
                    int e[8];
#pragma unroll
                    for (int u = 0; u < 8; u++) e[u] = widx[j - slab + u];
                    ull v[8];
#pragma unroll
                    for (int u = 0; u < 8; u++)
                        v[u] = __ldg(sh + (size_t)e[u] * 32 + lane);
#pragma unroll
                    for (int u = 0; u < 8; u++) {
                        u32 la = (u32)v[u], lb = (u32)(v[u] >> 32);
                        __half2 ha = *(__half2*)&la;
                        __half2 hb = *(__half2*)&lb;
                        float2 fa = __half22float2(ha);
                        float2 fb = __half22float2(hb);
                        add2(accA, pack2(fa.x, fa.y));
                        add2(accB, pack2(fb.x, fb.y));
                    }
                }
                for (; j < lim; j++) {
                    int e0 = widx[j - slab];
                    ull v0 = __ldg(sh + (size_t)e0 * 32 + lane);
                    u32 la = (u32)v0, lb = (u32)(v0 >> 32);
                    __half2 ha = *(__half2*)&la;
                    __half2 hb = *(__half2*)&lb;
                    float2 fa = __half22float2(ha);
                    float2 fb = __half22float2(hb);
                    add2(accA, pack2(fa.x, fa.y));
                    add2(accB, pack2(fb.x, fb.y));
                }
            }
            float2 sa = __ldg(s0 + (size_t)n * 32 + lane);   // exact fp32 own state
            float2 sb = __ldg(s1 + (size_t)n * 32 + lane);
            float2 aA = u2f2(accA), aB = u2f2(accB);
            ull* row = mx + m * 128;
            ((float4*)row)[lane]        = make_float4(sa.x, sb.x, sa.y, sb.y);
            ((float4*)(row + 64))[lane] = make_float4(aA.x, aB.x, aA.y, aB.y);
        }
        __syncwarp();

        // ---- FMA phase ----
        ull acc6[GROUP][4];
#pragma unroll
        for (int m = 0; m < GROUP; m++)
#pragma unroll
            for (int c = 0; c < 4; c++) acc6[m][c] = 0ull;

#pragma unroll 4
        for (int k = 0; k < 128; k += 2) {
            float4 wA = ((const float4*)(Ws + k * 128))[lane];
            float4 wB = ((const float4*)(Ws + (k + 1) * 128))[lane];
            ull wa0 = splat2(wA.x), wa1 = splat2(wA.y), wa2 = splat2(wA.z), wa3 = splat2(wA.w);
            ull wb0 = splat2(wB.x), wb1 = splat2(wB.y), wb2 = splat2(wB.z), wb3 = splat2(wB.w);
#pragma unroll
            for (int m = 0; m < GROUP; m++) {
                ulonglong2 xv = ((const ulonglong2*)(mx + m * 128))[k >> 1];
                fma2(acc6[m][0], wa0, xv.x); fma2(acc6[m][1], wa1, xv.x);
                fma2(acc6[m][2], wa2, xv.x); fma2(acc6[m][3], wa3, xv.x);
                fma2(acc6[m][0], wb0, xv.y); fma2(acc6[m][1], wb1, xv.y);
                fma2(acc6[m][2], wb2, xv.y); fma2(acc6[m][3], wb3, xv.y);
            }
        }

        // ---- epilogue ----
        for (int m = 0; m < cnt; m++) {
            int n = base + m;
            ull actp[4];
#pragma unroll
            for (int c = 0; c < 4; c++) {
                float2 pre = u2f2(acc6[m][c]);
                float p0 = pre.x + bias[c] + (flg[m] ? pj0[c] : 0.f);
                float p1 = pre.y + bias[c] + (flg[m] ? pj1[c] : 0.f);
                float a0, a1;
                if (zside) { a0 = sigm(p0);  a1 = sigm(p1); }
                else       { a0 = tanha(p0); a1 = tanha(p1); }
                actp[c] = pack2(a0, a1);
            }
            ull oth[4];
#pragma unroll
            for (int c = 0; c < 4; c++)
                oth[c] = __shfl_xor_sync(0xffffffffu, actp[c], 16);
            if (zside) {
                float4 r0, r1;
                float* q0 = (float*)&r0;
                float* q1 = (float*)&r1;
#pragma unroll
                for (int c = 0; c < 4; c++) {
                    float2 z = u2f2(actp[c]);
                    float2 t = u2f2(oth[c]);
                    float2 sp = u2f2(mx[m * 128 + cc0 + c]);
                    q0[c] = fmaf(z.x, t.x - sp.x, sp.x);
                    q1[c] = fmaf(z.y, t.y - sp.y, sp.y);
                }
                *((float4*)(out_ns + (size_t)n * 64 + cc0)) = r0;
                *((float4*)(out_ns + ((size_t)NN + n) * 64 + cc0)) = r1;
            }
        }
        __syncwarp();
    }
}

// ---------------- K4: readout + policy heads ----------------
__global__ void readout_kernel(const float* __restrict__ ns,
                               const int* __restrict__ efferent_idx,
                               const float* __restrict__ W_dec,
                               const float* __restrict__ b_dec,
                               const float* __restrict__ W_mean,
                               const float* __restrict__ b_mean,
                               const float* __restrict__ W_ls,
                               const float* __restrict__ b_ls,
                               float* __restrict__ out) {
    __shared__ float ro[NB * HH];
    __shared__ float dec[NB * HH];
    int t = threadIdx.x;
    int b = t >> 6, h = t & 63;
    float sum = 0.f;
    for (int i = 0; i < NEFF; i++) {
        int idx = efferent_idx[i];
        sum += ns[((size_t)b * NN + idx) * HH + h];
    }
    ro[b * HH + h] = sum * (1.f / NEFF);
    __syncthreads();
    float acc = b_dec[h];
    for (int k = 0; k < HH; k++)
        acc += ro[b * HH + k] * W_dec[k * HH + h];
    dec[b * HH + h] = tanhf(acc);
    __syncthreads();
    if (t < NB * NA) {
        int bb = t / NA, a = t % NA;
        float m = b_mean[a], ls = b_ls[a];
        for (int k = 0; k < HH; k++) {
            float d = dec[bb * HH + k];
            m  += d * W_mean[k * NA + a];
            ls += d * W_ls[k * NA + a];
        }
        ls = fminf(fmaxf(ls, -5.f), 2.f);
        out[bb * NA + a] = m;
        out[NB * NA + bb * NA + a] = ls;
    }
}

// ---------------- launch ----------------
extern "C" void kernel_launch(void* const* d_in, const int* in_sizes, int n_in,
                              void* d_out, int out_size) {
    const float* obs    = (const float*)d_in[0];
    const float* state  = (const float*)d_in[1];
    const float* W_in   = (const float*)d_in[2];
    const float* b_in   = (const float*)d_in[3];
    const float* W_msg  = (const float*)d_in[4];
    const float* W_gate = (const float*)d_in[5];
    const float* b_gate = (const float*)d_in[6];
    const float* W_cand = (const float*)d_in[7];
    const float* b_cand = (const float*)d_in[8];
    const float* W_dec  = (const float*)d_in[9];
    const float* b_dec  = (const float*)d_in[10];
    const float* W_mean = (const float*)d_in[11];
    const float* b_mean = (const float*)d_in[12];
    const float* W_ls   = (const float*)d_in[13];
    const float* b_ls   = (const float*)d_in[14];
    const int* src_idx  = (const int*)d_in[15];
    const int* dst_idx  = (const int*)d_in[16];
    const int* aff_idx  = (const int*)d_in[17];
    const int* eff_idx  = (const int*)d_in[18];
    float* out = (float*)d_out;
    float* out_ns = out + 2 * NB * NA;

    void *cntp = nullptr, *flagp = nullptr;
    cudaGetSymbolAddress(&cntp, g_cnt);
    cudaGetSymbolAddress(&flagp, g_flag);
    cudaMemsetAsync(cntp, 0, sizeof(int) * NN);
    cudaMemsetAsync(flagp, 0, sizeof(int) * NN);

    prep_small_kernel<<<1, 128>>>(obs, W_in, b_in, W_gate, W_cand, aff_idx);
    prep_W_kernel<<<128, 128>>>(W_msg, W_gate, W_cand);
    conv_kernel<<<(NN * 32 + 255) / 256, 256>>>(state);

    hist_kernel<<<(NE / 4 + 255) / 256, 256>>>((const int4*)dst_idx);
    scan_part_kernel<<<PB, 256>>>();
    scan_mid_kernel<<<1, 256>>>();
    scan_final_kernel<<<PB, 256>>>();
    scatter_kernel<<<(NE / 4 + 255) / 256, 256>>>((const int4*)src_idx, (const int4*)dst_idx);

    size_t smem = 16384u * 4 + (size_t)NW * GROUP * 128 * 8 + (size_t)NW * WIN * 4;  // 196608
    cudaFuncSetAttribute(fused_kernel, cudaFuncAttributeMaxDynamicSharedMemorySize, (int)smem);
    fused_kernel<<<NBLK, 512, smem>>>(state, b_gate, b_cand, out_ns);

    readout_kernel<<<1, 128>>>(out_ns, eff_idx, W_dec, b_dec, W_mean, b_mean, W_ls, b_ls, out);
}

// round 9
// speedup vs baseline: 1.8615x; 1.0239x over previous
#include <cuda_runtime.h>
#include <cstdint>
#include <cstdio>

#define NB   2
#define NN   50000
#define HH   64
#define NE   1000000
#define NOBS 128
#define NA   18
#define NAFF 512
#define NEFF 256
#define PB   196

#define NBLK   148
#define NW     16
#define WTOT   (NBLK * NW)     // 2368 warps
#define GROUP  6
#define WIN    512             // idx window (ints) per warp

// chunk split: NN = WTOT*21 + 272  ->  first 272 warps take 22 nodes
#define CHUNK_BIG   22
#define CHUNK_SMALL 21
#define NBIG        (NN - WTOT * CHUNK_SMALL)   // 272

typedef unsigned int u32;
typedef unsigned long long ull;

// ---------------- device scratch ----------------
__device__ float g_Wp[128 * 128];             // fused weight
__device__ float g_projG[NB * HH];
__device__ float g_projC[NB * HH];
__device__ int   g_flag[NN];
__device__ int   g_cnt[NN];
__device__ int   g_off[NN + 1];
__device__ int   g_cur[NN];
__device__ int   g_esrc[NE + WIN];            // padded for cp.async overread
__device__ int   g_part[256];
__device__ int   g_base[256];

// ---------------- helpers ----------------
__device__ __forceinline__ void fma2(ull& d, ull a, ull b) {
    asm("fma.rn.f32x2 %0, %1, %2, %0;" : "+l"(d) : "l"(a), "l"(b));
}
__device__ __forceinline__ ull splat2(float w) {
    ull r; unsigned u = __float_as_uint(w);
    asm("mov.b64 %0, {%1, %1};" : "=l"(r) : "r"(u));
    return r;
}
__device__ __forceinline__ ull pack2(float a, float b) {
    ull r;
    asm("mov.b64 %0, {%1, %2};" : "=l"(r) : "r"(__float_as_uint(a)), "r"(__float_as_uint(b)));
    return r;
}
__device__ __forceinline__ float2 u2f2(ull v) {
    float2 f;
    f.x = __uint_as_float((unsigned)v);
    f.y = __uint_as_float((unsigned)(v >> 32));
    return f;
}
__device__ __forceinline__ void cpa16(void* dst, const void* src) {
    unsigned d = (unsigned)__cvta_generic_to_shared(dst);
    asm volatile("cp.async.cg.shared.global [%0], [%1], 16;" :: "r"(d), "l"(src));
}
__device__ __forceinline__ int warp_incl_scan(int v) {
    int lane = threadIdx.x & 31;
#pragma unroll
    for (int d = 1; d < 32; d <<= 1) {
        int t = __shfl_up_sync(0xffffffffu, v, d);
        if (lane >= d) v += t;
    }
    return v;
}
__device__ __forceinline__ float sigm(float x) { return __fdividef(1.f, 1.f + __expf(-x)); }
__device__ __forceinline__ float tanha(float x) { return 1.f - __fdividef(2.f, __expf(2.f * x) + 1.f); }

// ---------------- K1: merged prep (small proj + fused weight) ----------------
__global__ void prep_kernel(const float* __restrict__ obs,
                            const float* __restrict__ W_in,
                            const float* __restrict__ b_in,
                            const float* __restrict__ W_msg,
                            const float* __restrict__ W_gate,
                            const float* __restrict__ W_cand,
                            const int* __restrict__ afferent_idx) {
    if (blockIdx.x == 128) {
        // projections + flags
        __shared__ float proj[NB * HH];
        int t = threadIdx.x;            // 128 threads
        int b = t >> 6, h = t & 63;
        float acc = b_in[h];
        for (int o = 0; o < NOBS; o++)
            acc += obs[b * NOBS + o] * W_in[o * HH + h];
        proj[b * HH + h] = acc;
        __syncthreads();
        float ag = 0.f, ac = 0.f;
        for (int k = 0; k < HH; k++) {
            float p = proj[b * HH + k];
            ag += p * W_gate[(HH + k) * HH + h];
            ac += p * W_cand[(HH + k) * HH + h];
        }
        g_projG[b * HH + h] = ag;
        g_projC[b * HH + h] = ac;
        for (int i = t; i < NAFF; i += 128)
            g_flag[afferent_idx[i]] = 1;
    } else {
        int c = blockIdx.x;     // output column 0..127
        int k = threadIdx.x;    // input row 0..127
        float w;
        if (k < HH) {
            w = (c < HH) ? W_gate[k * HH + c] : W_cand[k * HH + (c - HH)];
        } else {
            int km = k - HH;
            float acc = 0.f;
            if (c < HH) {
                for (int t = 0; t < HH; t++)
                    acc += W_msg[km * HH + t] * W_gate[(HH + t) * HH + c];
            } else {
                for (int t = 0; t < HH; t++)
                    acc += W_msg[km * HH + t] * W_cand[(HH + t) * HH + (c - HH)];
            }
            w = acc;
        }
        g_Wp[k * 128 + c] = w;
    }
}

// ---------------- CSR build ----------------
__global__ void hist_kernel(const int4* __restrict__ dst4) {
    int i = (blockIdx.x * blockDim.x + threadIdx.x) * 2;
    if (i < NE / 4) {
        int4 d0 = __ldg(dst4 + i);
        int4 d1 = __ldg(dst4 + i + 1);
        atomicAdd(&g_cnt[d0.x], 1);
        atomicAdd(&g_cnt[d0.y], 1);
        atomicAdd(&g_cnt[d0.z], 1);
        atomicAdd(&g_cnt[d0.w], 1);
        atomicAdd(&g_cnt[d1.x], 1);
        atomicAdd(&g_cnt[d1.y], 1);
        atomicAdd(&g_cnt[d1.z], 1);
        atomicAdd(&g_cnt[d1.w], 1);
    }
}

__global__ void scan_part_kernel() {
    int i = blockIdx.x * 256 + threadIdx.x;
    int v = (i < NN) ? g_cnt[i] : 0;
    __shared__ int ws[8];
    int s = v;
#pragma unroll
    for (int d = 16; d > 0; d >>= 1) s += __shfl_down_sync(0xffffffffu, s, d);
    if ((threadIdx.x & 31) == 0) ws[threadIdx.x >> 5] = s;
    __syncthreads();
    if (threadIdx.x == 0) {
        int tot = 0;
        for (int w = 0; w < 8; w++) tot += ws[w];
        g_part[blockIdx.x] = tot;
    }
}

__global__ void scan_mid_kernel() {
    int t = threadIdx.x;
    int lane = t & 31, w = t >> 5;
    int v = (t < PB) ? g_part[t] : 0;
    int inc = warp_incl_scan(v);
    __shared__ int ws[8];
    if (lane == 31) ws[w] = inc;
    __syncthreads();
    if (w == 0) {
        int q = (lane < 8) ? ws[lane] : 0;
        int qi = warp_incl_scan(q);
        if (lane < 8) ws[lane] = qi;
    }
    __syncthreads();
    int base = (w > 0) ? ws[w - 1] : 0;
    g_base[t] = base + inc - v;
}

__global__ void scan_final_kernel() {
    int i = blockIdx.x * 256 + threadIdx.x;
    int t = threadIdx.x;
    int lane = t & 31, w = t >> 5;
    int v = (i < NN) ? g_cnt[i] : 0;
    int inc = warp_incl_scan(v);
    __shared__ int ws[8];
    if (lane == 31) ws[w] = inc;
    __syncthreads();
    if (w == 0) {
        int q = (lane < 8) ? ws[lane] : 0;
        int qi = warp_incl_scan(q);
        if (lane < 8) ws[lane] = qi;
    }
    __syncthreads();
    int base = (w > 0) ? ws[w - 1] : 0;
    int off = g_base[blockIdx.x] + base + inc - v;
    if (i < NN) { g_off[i] = off; g_cur[i] = off; }
    if (i == 0) g_off[NN] = NE;
}

__global__ void scatter_kernel(const int4* __restrict__ src4,
                               const int4* __restrict__ dst4) {
    int i = (blockIdx.x * blockDim.x + threadIdx.x) * 2;
    if (i < NE / 4) {
        int4 s0 = __ldg(src4 + i);
        int4 d0 = __ldg(dst4 + i);
        int4 s1 = __ldg(src4 + i + 1);
        int4 d1 = __ldg(dst4 + i + 1);
        g_esrc[atomicAdd(&g_cur[d0.x], 1)] = s0.x;
        g_esrc[atomicAdd(&g_cur[d0.y], 1)] = s0.y;
        g_esrc[atomicAdd(&g_cur[d0.z], 1)] = s0.z;
        g_esrc[atomicAdd(&g_cur[d0.w], 1)] = s0.w;
        g_esrc[atomicAdd(&g_cur[d1.x], 1)] = s1.x;
        g_esrc[atomicAdd(&g_cur[d1.y], 1)] = s1.y;
        g_esrc[atomicAdd(&g_cur[d1.z], 1)] = s1.z;
        g_esrc[atomicAdd(&g_cur[d1.w], 1)] = s1.w;
    }
}

// ---------------- K2: fused gather + f32x2 GEMM + GRU epilogue ----------------
// 16 warps/block, 1 block/SM, no block syncs in the loop. Each warp owns a
// CONTIGUOUS ~21-node chunk; its first sub-group has 1+(gwid%6) nodes (stagger)
// then groups of 6. Chunks keep the CSR slab in one smem window; stagger
// desynchronizes warps so gather (LTS) and FMA (fma pipe) overlap.
__global__ void __launch_bounds__(512, 1) fused_kernel(const float* __restrict__ state,
                                                       const float* __restrict__ b_gate,
                                                       const float* __restrict__ b_cand,
                                                       float* __restrict__ out_ns) {
    extern __shared__ float smem[];
    float* Ws = smem;                                    // 16384 floats
    ull* xs = (ull*)(smem + 16384);                      // NW * GROUP * 128 ull
    int* sIdx = (int*)(xs + NW * GROUP * 128);           // NW * WIN ints

    int tid = threadIdx.x;
    for (int i = tid; i < 4096; i += 512)
        ((float4*)Ws)[i] = ((const float4*)g_Wp)[i];
    __syncthreads();

    int warp = tid >> 5, lane = tid & 31;
    int q = lane & 15;
    int cc0 = q * 4;
    bool zside = lane < 16;

    float bias[4], pj0[4], pj1[4];
#pragma unroll
    for (int c = 0; c < 4; c++) {
        int cc = cc0 + c;
        if (zside) { bias[c] = __ldg(b_gate + cc); pj0[c] = g_projG[cc]; pj1[c] = g_projG[64 + cc]; }
        else       { bias[c] = __ldg(b_cand + cc); pj0[c] = g_projC[cc]; pj1[c] = g_projC[64 + cc]; }
    }

    ull* mx = xs + warp * (GROUP * 128);
    int* widx = sIdx + warp * WIN;
    int gwid = blockIdx.x * NW + warp;
    const float2* s0 = (const float2*)state;
    const float2* s1 = s0 + (size_t)NN * 32;

    // contiguous chunk for this warp
    int cBase, cCnt;
    if (gwid < NBIG) { cBase = gwid * CHUNK_BIG; cCnt = CHUNK_BIG; }
    else             { cBase = NBIG * CHUNK_BIG + (gwid - NBIG) * CHUNK_SMALL; cCnt = CHUNK_SMALL; }
    int nEnd = cBase + cCnt;

    // stage index window for the chunk (covers ~440 edges typically)
    int slab = __ldg(&g_off[cBase]) & ~3;
    for (int c = lane; c < WIN / 4; c += 32)
        cpa16(widx + c * 4, g_esrc + slab + c * 4);
    asm volatile("cp.async.commit_group;" ::: "memory");
    asm volatile("cp.async.wait_group 0;" ::: "memory");
    __syncwarp();

    int sg = 1 + (gwid % GROUP);       // staggered first sub-group size
    int n0 = cBase;
    while (n0 < nEnd) {
        int cnt = nEnd - n0;
        if (cnt > sg) cnt = sg;
        sg = GROUP;
        int flg[GROUP];

        // ---- gather phase ----
        for (int m = 0; m < cnt; m++) {
            int n = n0 + m;
            int beg = __ldg(&g_off[n]), end = __ldg(&g_off[n + 1]);
            flg[m] = __ldg(&g_flag[n]);
            float4 acc = make_float4(0.f, 0.f, 0.f, 0.f);
            int j = beg;
            while (j < end) {
                if (j >= slab + WIN) {           // refill window (rare)
                    slab = j & ~3;
                    for (int c = lane; c < WIN / 4; c += 32)
                        cpa16(widx + c * 4, g_esrc + slab + c * 4);
                    asm volatile("cp.async.commit_group;" ::: "memory");
                    asm volatile("cp.async.wait_group 0;" ::: "memory");
                    __syncwarp();
                }
                int lim = slab + WIN;
                if (lim > end) lim = end;
                for (; j + 8 <= lim; j += 8) {
                    int e[8];
#pragma unroll
                    for (int u = 0; u < 8; u++) e[u] = widx[j - slab + u];
                    float2 av[8], bv[8];
#pragma unroll
                    for (int u = 0; u < 8; u++) {
                        av[u] = __ldg(s0 + (size_t)e[u] * 32 + lane);
                        bv[u] = __ldg(s1 + (size_t)e[u] * 32 + lane);
                    }
#pragma unroll
                    for (int u = 0; u < 8; u++) {
                        acc.x += av[u].x; acc.y += av[u].y;
                        acc.z += bv[u].x; acc.w += bv[u].y;
                    }
                }
                for (; j < lim; j++) {
                    int e0 = widx[j - slab];
                    float2 a = __ldg(s0 + (size_t)e0 * 32 + lane);
                    float2 b = __ldg(s1 + (size_t)e0 * 32 + lane);
                    acc.x += a.x; acc.y += a.y; acc.z += b.x; acc.w += b.y;
                }
            }
            float2 sa = __ldg(s0 + (size_t)n * 32 + lane);
            float2 sb = __ldg(s1 + (size_t)n * 32 + lane);
            ull* row = mx + m * 128;
            ((float4*)row)[lane]        = make_float4(sa.x, sb.x, sa.y, sb.y);
            ((float4*)(row + 64))[lane] = make_float4(acc.x, acc.z, acc.y, acc.w);
        }
        __syncwarp();

        // ---- FMA phase (fixed GROUP unroll; rows >= cnt are garbage, unused) ----
        ull acc6[GROUP][4];
#pragma unroll
        for (int m = 0; m < GROUP; m++)
#pragma unroll
            for (int c = 0; c < 4; c++) acc6[m][c] = 0ull;

#pragma unroll 4
        for (int k = 0; k < 128; k += 2) {
            float4 wA = ((const float4*)(Ws + k * 128))[lane];
            float4 wB = ((const float4*)(Ws + (k + 1) * 128))[lane];
            ull wa0 = splat2(wA.x), wa1 = splat2(wA.y), wa2 = splat2(wA.z), wa3 = splat2(wA.w);
            ull wb0 = splat2(wB.x), wb1 = splat2(wB.y), wb2 = splat2(wB.z), wb3 = splat2(wB.w);
#pragma unroll
            for (int m = 0; m < GROUP; m++) {
                ulonglong2 xv = ((const ulonglong2*)(mx + m * 128))[k >> 1];
                fma2(acc6[m][0], wa0, xv.x); fma2(acc6[m][1], wa1, xv.x);
                fma2(acc6[m][2], wa2, xv.x); fma2(acc6[m][3], wa3, xv.x);
                fma2(acc6[m][0], wb0, xv.y); fma2(acc6[m][1], wb1, xv.y);
                fma2(acc6[m][2], wb2, xv.y); fma2(acc6[m][3], wb3, xv.y);
            }
        }

        // ---- epilogue ----
        for (int m = 0; m < cnt; m++) {
            int n = n0 + m;
            ull actp[4];
#pragma unroll
            for (int c = 0; c < 4; c++) {
                float2 pre = u2f2(acc6[m][c]);
                float p0 = pre.x + bias[c] + (flg[m] ? pj0[c] : 0.f);
                float p1 = pre.y + bias[c] + (flg[m] ? pj1[c] : 0.f);
                float a0, a1;
                if (zside) { a0 = sigm(p0);  a1 = sigm(p1); }
                else       { a0 = tanha(p0); a1 = tanha(p1); }
                actp[c] = pack2(a0, a1);
            }
            ull oth[4];
#pragma unroll
            for (int c = 0; c < 4; c++)
                oth[c] = __shfl_xor_sync(0xffffffffu, actp[c], 16);
            if (zside) {
                float4 r0, r1;
                float* q0 = (float*)&r0;
                float* q1 = (float*)&r1;
#pragma unroll
                for (int c = 0; c < 4; c++) {
                    float2 z = u2f2(actp[c]);
                    float2 t = u2f2(oth[c]);
                    float2 sp = u2f2(mx[m * 128 + cc0 + c]);
                    q0[c] = fmaf(z.x, t.x - sp.x, sp.x);
                    q1[c] = fmaf(z.y, t.y - sp.y, sp.y);
                }
                *((float4*)(out_ns + (size_t)n * 64 + cc0)) = r0;
                *((float4*)(out_ns + ((size_t)NN + n) * 64 + cc0)) = r1;
            }
        }
        __syncwarp();
        n0 += cnt;
    }
}

// ---------------- K4: readout + policy heads ----------------
__global__ void readout_kernel(const float* __restrict__ ns,
                               const int* __restrict__ efferent_idx,
                               const float* __restrict__ W_dec,
                               const float* __restrict__ b_dec,
                               const float* __restrict__ W_mean,
                               const float* __restrict__ b_mean,
                               const float* __restrict__ W_ls,
                               const float* __restrict__ b_ls,
                               float* __restrict__ out) {
    __shared__ float ro[NB * HH];
    __shared__ float dec[NB * HH];
    int t = threadIdx.x;
    int b = t >> 6, h = t & 63;
    float sum = 0.f;
    for (int i = 0; i < NEFF; i++) {
        int idx = efferent_idx[i];
        sum += ns[((size_t)b * NN + idx) * HH + h];
    }
    ro[b * HH + h] = sum * (1.f / NEFF);
    __syncthreads();
    float acc = b_dec[h];
    for (int k = 0; k < HH; k++)
        acc += ro[b * HH + k] * W_dec[k * HH + h];
    dec[b * HH + h] = tanhf(acc);
    __syncthreads();
    if (t < NB * NA) {
        int bb = t / NA, a = t % NA;
        float m = b_mean[a], ls = b_ls[a];
        for (int k = 0; k < HH; k++) {
            float d = dec[bb * HH + k];
            m  += d * W_mean[k * NA + a];
            ls += d * W_ls[k * NA + a];
        }
        ls = fminf(fmaxf(ls, -5.f), 2.f);
        out[bb * NA + a] = m;
        out[NB * NA + bb * NA + a] = ls;
    }
}

// ---------------- launch ----------------
extern "C" void kernel_launch(void* const* d_in, const int* in_sizes, int n_in,
                              void* d_out, int out_size) {
    const float* obs    = (const float*)d_in[0];
    const float* state  = (const float*)d_in[1];
    const float* W_in   = (const float*)d_in[2];
    const float* b_in   = (const float*)d_in[3];
    const float* W_msg  = (const float*)d_in[4];
    const float* W_gate = (const float*)d_in[5];
    const float* b_gate = (const float*)d_in[6];
    const float* W_cand = (const float*)d_in[7];
    const float* b_cand = (const float*)d_in[8];
    const float* W_dec  = (const float*)d_in[9];
    const float* b_dec  = (const float*)d_in[10];
    const float* W_mean = (const float*)d_in[11];
    const float* b_mean = (const float*)d_in[12];
    const float* W_ls   = (const float*)d_in[13];
    const float* b_ls   = (const float*)d_in[14];
    const int* src_idx  = (const int*)d_in[15];
    const int* dst_idx  = (const int*)d_in[16];
    const int* aff_idx  = (const int*)d_in[17];
    const int* eff_idx  = (const int*)d_in[18];
    float* out = (float*)d_out;
    float* out_ns = out + 2 * NB * NA;

    void *cntp = nullptr, *flagp = nullptr;
    cudaGetSymbolAddress(&cntp, g_cnt);
    cudaGetSymbolAddress(&flagp, g_flag);
    cudaMemsetAsync(cntp, 0, sizeof(int) * NN);
    cudaMemsetAsync(flagp, 0, sizeof(int) * NN);

    prep_kernel<<<129, 128>>>(obs, W_in, b_in, W_msg, W_gate, W_cand, aff_idx);

    hist_kernel<<<(NE / 8 + 255) / 256, 256>>>((const int4*)dst_idx);
    scan_part_kernel<<<PB, 256>>>();
    scan_mid_kernel<<<1, 256>>>();
    scan_final_kernel<<<PB, 256>>>();
    scatter_kernel<<<(NE / 8 + 255) / 256, 256>>>((const int4*)src_idx, (const int4*)dst_idx);

    size_t smem = 16384u * 4 + (size_t)NW * GROUP * 128 * 8 + (size_t)NW * WIN * 4;  // 196608
    cudaFuncSetAttribute(fused_kernel, cudaFuncAttributeMaxDynamicSharedMemorySize, (int)smem);
    fused_kernel<<<NBLK, 512, smem>>>(state, b_gate, b_cand, out_ns);

    readout_kernel<<<1, 128>>>(out_ns, eff_idx, W_dec, b_dec, W_mean, b_mean, W_ls, b_ls, out);
}